// round 8
// baseline (speedup 1.0000x reference)
#include <cuda_runtime.h>
#include <math.h>

#define BB 8
#define CC 64
#define NNODE 1000
#define TT 24

// ---------------- scratch (device globals; no allocation) ----------------
__device__ float g_proj [BB*NNODE*20];          // shared proj buffer for all 3 attentions
__device__ float g_att0A[BB*64*64];
__device__ float g_tattA[BB*24*24];
__device__ float g_Ag   [BB*NNODE*NNODE];       // 32 MB
__device__ float g_x1   [BB*CC*NNODE*TT];       // 49 MB  [b][c][n][t]
__device__ float g_xw   [BB*NNODE*CC*TT];       // 49 MB  [b][m][o][t]
__device__ float g_g2   [BB*NNODE*CC*TT];       // 49 MB  [b][n][o][t]
__device__ float g_res  [BB*NNODE*CC*TT];       // 49 MB  [b][n][o][t]
__device__ float g_x2b  [BB*NNODE*CC*TT];       // 49 MB
__device__ float g_part [BB*250*480];           // tatt split-K partials

// ---------------- 1. generic row projection: proj[b][row][0:10]=X@W1, [10:20]=W2@X
__global__ void k_proj(const float* __restrict__ X, const float* __restrict__ W1,
                       const float* __restrict__ W2, float* __restrict__ proj,
                       int K, int rowStride, long batchStride, int inner, int strideC)
{
    int b = blockIdx.y, r = blockIdx.x;
    const float* base = X + (long)b*batchStride + (long)r*rowStride;
    float acc[20];
#pragma unroll
    for (int i = 0; i < 20; i++) acc[i] = 0.f;
    for (int k = threadIdx.x; k < K; k += 256) {
        int c = k / inner, t = k - c*inner;
        float xv = base[(long)c*strideC + t];
        const float* w1 = W1 + (long)k*10;
#pragma unroll
        for (int j = 0; j < 10; j++) acc[j]    += xv * w1[j];
#pragma unroll
        for (int j = 0; j < 10; j++) acc[10+j] += xv * W2[(long)j*K + k];
    }
    __shared__ float red[8][20];
    int lane = threadIdx.x & 31, w = threadIdx.x >> 5;
#pragma unroll
    for (int j = 0; j < 20; j++) {
        float v = acc[j];
#pragma unroll
        for (int s = 16; s > 0; s >>= 1) v += __shfl_xor_sync(0xffffffffu, v, s);
        if (lane == 0) red[w][j] = v;
    }
    __syncthreads();
    if (threadIdx.x < 20) {
        float s = 0.f;
#pragma unroll
        for (int q = 0; q < 8; q++) s += red[q][threadIdx.x];
        proj[((long)b*NNODE + r)*20 + threadIdx.x] = s;
    }
}

// ---------------- 2. scores + softmax (+ optional elementwise adj): out[b][i][j]
__global__ void k_scores(const float* __restrict__ proj, const float* __restrict__ adj,
                         float* __restrict__ out, int L, float scale)
{
    int b = blockIdx.y, i = blockIdx.x;
    __shared__ float p1[10];
    __shared__ float smax[8], ssum[8];
    int tid = threadIdx.x;
    if (tid < 10) p1[tid] = proj[((long)b*NNODE + i)*20 + tid];
    __syncthreads();
    float sv[4];
    float mx = -1e30f;
#pragma unroll
    for (int q = 0; q < 4; q++) {
        int j = tid + q*256;
        float s = -1e30f;
        if (j < L) {
            const float* p2 = proj + ((long)b*NNODE + j)*20 + 10;
            s = 0.f;
#pragma unroll
            for (int r = 0; r < 10; r++) s += p1[r]*p2[r];
            s *= scale;
        }
        sv[q] = s;
        mx = fmaxf(mx, s);
    }
    int lane = tid & 31, w = tid >> 5;
#pragma unroll
    for (int s = 16; s > 0; s >>= 1) mx = fmaxf(mx, __shfl_xor_sync(0xffffffffu, mx, s));
    if (lane == 0) smax[w] = mx;
    __syncthreads();
    mx = smax[0];
#pragma unroll
    for (int q = 1; q < 8; q++) mx = fmaxf(mx, smax[q]);
    float lsum = 0.f;
#pragma unroll
    for (int q = 0; q < 4; q++) {
        int j = tid + q*256;
        float e = (j < L) ? __expf(sv[q] - mx) : 0.f;
        sv[q] = e;
        lsum += e;
    }
#pragma unroll
    for (int s = 16; s > 0; s >>= 1) lsum += __shfl_xor_sync(0xffffffffu, lsum, s);
    if (lane == 0) ssum[w] = lsum;
    __syncthreads();
    lsum = 0.f;
#pragma unroll
    for (int q = 0; q < 8; q++) lsum += ssum[q];
    float inv = 1.f/lsum;
#pragma unroll
    for (int q = 0; q < 4; q++) {
        int j = tid + q*256;
        if (j < L) {
            float v = sv[q]*inv;
            if (adj) v *= adj[(long)i*L + j];
            out[((long)b*L + i)*L + j] = v;
        }
    }
}

// ---------------- 3. batched SGEMM (f32x2, double-buffered, 1 sync/iter)
// C[M,N]=A[M,K]@B[K,N]; BM=128, BN=128, BK=8; K%8==0, N%4==0, cols handled in 8s.
// 256 threads, 8x8 microtile per thread, packed fma.rn.f32x2 accumulators.
__global__ void __launch_bounds__(256) k_sgemm(
    const float* __restrict__ A, const float* __restrict__ Bm, float* __restrict__ C,
    int M, int N, int K, long sA, long sB, long sC)
{
    __shared__ __align__(16) float As[2][8][128];
    __shared__ __align__(16) float Bs[2][8][128];
    int b = blockIdx.z;
    const float* Ab = A + (long)b*sA;
    const float* Bb = Bm + (long)b*sB;
    float* Cb = C + (long)b*sC;
    int row0 = blockIdx.y*128, col0 = blockIdx.x*128;
    int tid = threadIdx.x;
    int tx = tid & 15, ty = tid >> 4;         // 16x16 thread grid, 8x8 microtile
    int ar = tid >> 1, aq = tid & 1;          // A loader: row ar (0..127), k-half aq
    int bk = tid >> 5, bc = tid & 31;         // B loader: k-row bk (0..7), col group bc
    bool aok = (row0 + ar < M);
    int bcol = col0 + bc*4;
    bool bok = (bcol < N);
    const float* Ap = Ab + (long)(row0+ar)*K + aq*4;
    const float* Bp = Bb + (long)bk*N + bcol;

    unsigned long long acc2[8][4];
#pragma unroll
    for (int i = 0; i < 8; i++)
#pragma unroll
        for (int q = 0; q < 4; q++) acc2[i][q] = 0ull;

    // prologue: load k-slice 0
    float4 av = make_float4(0.f,0.f,0.f,0.f);
    float4 bv = av;
    if (aok) av = *(const float4*)Ap;
    if (bok) bv = *(const float4*)Bp;
    As[0][aq*4+0][ar] = av.x; As[0][aq*4+1][ar] = av.y;
    As[0][aq*4+2][ar] = av.z; As[0][aq*4+3][ar] = av.w;
    *(float4*)&Bs[0][bk][bc*4] = bv;
    __syncthreads();

    int buf = 0;
    for (int k0 = 0; k0 < K; k0 += 8) {
        // issue global loads for next slice (hidden behind compute below)
        bool more = (k0 + 8 < K);
        if (more) {
            av = make_float4(0.f,0.f,0.f,0.f);
            bv = av;
            if (aok) av = *(const float4*)(Ap + k0 + 8);
            if (bok) bv = *(const float4*)(Bp + (long)(k0+8)*N);
        }
        // compute current slice
#pragma unroll
        for (int kk = 0; kk < 8; kk++) {
            float a[8];
            *(float4*)&a[0] = *(const float4*)&As[buf][kk][ty*8];
            *(float4*)&a[4] = *(const float4*)&As[buf][kk][ty*8+4];
            unsigned long long bp2[4];
#pragma unroll
            for (int q = 0; q < 4; q++)
                bp2[q] = *(const unsigned long long*)&Bs[buf][kk][tx*8 + q*2];
#pragma unroll
            for (int i = 0; i < 8; i++) {
                unsigned long long ap;
                asm("mov.b64 %0, {%1, %1};" : "=l"(ap) : "r"(__float_as_uint(a[i])));
#pragma unroll
                for (int q = 0; q < 4; q++)
                    asm("fma.rn.f32x2 %0, %1, %2, %0;"
                        : "+l"(acc2[i][q]) : "l"(ap), "l"(bp2[q]));
            }
        }
        if (more) {
            // single barrier is sufficient: the store targets buf^1, whose last
            // readers were drained by the PREVIOUS iteration's barrier; current
            // compute touched only buf.
            int nb = buf ^ 1;
            As[nb][aq*4+0][ar] = av.x; As[nb][aq*4+1][ar] = av.y;
            As[nb][aq*4+2][ar] = av.z; As[nb][aq*4+3][ar] = av.w;
            *(float4*)&Bs[nb][bk][bc*4] = bv;
            __syncthreads();
            buf = nb;
        }
    }
#pragma unroll
    for (int i = 0; i < 8; i++) {
        int row = row0 + ty*8 + i;
        if (row >= M) continue;
        float c[8];
#pragma unroll
        for (int q = 0; q < 4; q++) {
            float2 v = *(float2*)&acc2[i][q];
            c[q*2] = v.x; c[q*2+1] = v.y;
        }
        int col = col0 + tx*8;
        if (col < N) {
            *(float4*)&Cb[(long)row*N + col]     = *(float4*)&c[0];
            *(float4*)&Cb[(long)row*N + col + 4] = *(float4*)&c[4];
        }
    }
}

// ---------------- 4. channel mix: out[b][m][o][t] = bias[o] + sum_c W(c,o)*X[b][c][m][t]
__global__ void k_chanmix(const float* __restrict__ X, const float* __restrict__ W,
                          const float* __restrict__ bias, float* __restrict__ out, int trans)
{
    __shared__ float Ws[64*64];
    __shared__ __align__(16) float xs[4][64][24];
    int b = blockIdx.y, m0 = blockIdx.x*4;
    int tid = threadIdx.x;
    for (int e = tid; e < 4096; e += 256) {
        int c = e >> 6, o = e & 63;
        Ws[e] = trans ? W[o*64 + c] : W[e];
    }
    for (int e = tid; e < 6144; e += 256) {
        int mi = e / 1536, rem = e - mi*1536, c = rem / 24, t = rem - c*24;
        xs[mi][c][t] = X[(((long)b*64 + c)*1000 + (m0+mi))*24 + t];
    }
    __syncthreads();
    int o = tid & 63, mi = tid >> 6;
    float bv = bias ? bias[o] : 0.f;
    float acc[24];
#pragma unroll
    for (int t = 0; t < 24; t++) acc[t] = bv;
#pragma unroll 4
    for (int c = 0; c < 64; c++) {
        float w = Ws[c*64 + o];
        float xv[24];
        const float4* xr = (const float4*)xs[mi][c];
#pragma unroll
        for (int q = 0; q < 6; q++) *(float4*)&xv[q*4] = xr[q];
#pragma unroll
        for (int t = 0; t < 24; t++) acc[t] += w*xv[t];
    }
    float* op = &out[(((long)b*1000 + m0+mi)*64 + o)*24];
#pragma unroll
    for (int q = 0; q < 6; q++) *(float4*)&op[q*4] = *(float4*)&acc[q*4];
}

// ---------------- 5. tatt split-K proj: partials over k-chunks of 256
__global__ void k_proj_tatt(const float* __restrict__ G, const float* __restrict__ W1,
                            const float* __restrict__ W2, float* __restrict__ part)
{
    __shared__ __align__(16) float Gs[256][24];
    __shared__ float Ws[256][20];
    int b = blockIdx.y;
    int k0 = blockIdx.x*256;
    int tid = threadIdx.x;
    const float* Gb = G + (long)b*64000*24 + (long)k0*24;
    for (int e = tid; e < 6144; e += 256) ((float*)Gs)[e] = Gb[e];
    for (int e = tid; e < 5120; e += 256) {
        int kk = e / 20, j = e - kk*20;
        Ws[kk][j] = (j < 10) ? W1[(long)(k0+kk)*10 + j]
                             : W2[(long)(j-10)*64000 + (k0+kk)];
    }
    __syncthreads();
    for (int task = tid; task < 480; task += 256) {
        int t = task / 20, j = task - t*20;
        float s = 0.f;
#pragma unroll 8
        for (int kk = 0; kk < 256; kk++) s += Gs[kk][t]*Ws[kk][j];
        part[((long)b*250 + blockIdx.x)*480 + task] = s;
    }
}

__global__ void k_reduce_tatt(const float* __restrict__ part, float* __restrict__ proj)
{
    int b = blockIdx.x;
    int task = threadIdx.x;              // blockDim = 480
    float s = 0.f;
    for (int ch = 0; ch < 250; ch++) s += part[((long)b*250 + ch)*480 + task];
    int t = task / 20, j = task - t*20;
    proj[((long)b*NNODE + t)*20 + j] = s;
}

// ---------------- 6. conv1 fused with tatt apply: per block 2 nodes
// xs <- g2 tile; xs <- xs @ tattA^T (temporal mix per row); conv1 (d=1) + bias + relu
__global__ void k_conv1t(const float* __restrict__ X, const float* __restrict__ TA,
                         const float* __restrict__ Wc, const float* __restrict__ bias,
                         float* __restrict__ Y)
{
    __shared__ float ws[64][2][64];               // [c][tap][o]
    __shared__ __align__(16) float xs[2][64][24];
    __shared__ __align__(16) float AsT[24][24];   // AsT[t'][t] = TA[b][t][t']
    int b = blockIdx.y, n0 = blockIdx.x*2;
    int tid = threadIdx.x;                        // 128
    for (int e = tid; e < 576; e += 128) {
        int t = e / 24, tp = e - t*24;
        AsT[tp][t] = TA[(long)b*576 + t*24 + tp];
    }
    for (int e = tid; e < 8192; e += 128) {
        int c = e >> 7, tap = (e >> 6) & 1, o = e & 63;
        ws[c][tap][o] = Wc[(o << 7) + (c << 1) + tap];
    }
    for (int e = tid; e < 3072; e += 128)
        ((float*)xs)[e] = X[((long)b*1000 + n0)*1536 + e];
    __syncthreads();
    // temporal attention mix: each thread owns one row of xs (128 rows total)
    {
        float* row = &xs[tid >> 6][tid & 63][0];
        float xv[24], accm[24];
#pragma unroll
        for (int q = 0; q < 6; q++) *(float4*)&xv[q*4] = *(const float4*)&row[q*4];
#pragma unroll
        for (int t = 0; t < 24; t++) accm[t] = 0.f;
#pragma unroll
        for (int tp = 0; tp < 24; tp++) {
            float v = xv[tp];
            const float4* ar = (const float4*)AsT[tp];
            float avv[24];
#pragma unroll
            for (int q = 0; q < 6; q++) *(float4*)&avv[q*4] = ar[q];
#pragma unroll
            for (int t = 0; t < 24; t++) accm[t] += v*avv[t];
        }
#pragma unroll
        for (int q = 0; q < 6; q++) *(float4*)&row[q*4] = *(float4*)&accm[q*4];
    }
    __syncthreads();
    int o = tid & 63, ni = tid >> 6;
    float bv = bias[o];
    float acc[24];
#pragma unroll
    for (int t = 0; t < 24; t++) acc[t] = bv;
#pragma unroll 2
    for (int c = 0; c < 64; c++) {
        float w0 = ws[c][0][o], w1 = ws[c][1][o];
        float xv[24];
        const float4* xr = (const float4*)xs[ni][c];
#pragma unroll
        for (int q = 0; q < 6; q++) *(float4*)&xv[q*4] = xr[q];
        acc[0] += w1*xv[0];
#pragma unroll
        for (int t = 1; t < 24; t++) acc[t] += w1*xv[t] + w0*xv[t-1];
    }
    float* op = &Y[(((long)b*1000 + n0+ni)*64 + o)*24];
#pragma unroll
    for (int t = 0; t < 24; t++) acc[t] = fmaxf(acc[t], 0.f);
#pragma unroll
    for (int q = 0; q < 6; q++) *(float4*)&op[q*4] = *(float4*)&acc[q*4];
}

// ---------------- 7. conv2 (d=2) + bias + relu + residual + relu + LayerNorm(channel)
__global__ void k_final(const float* __restrict__ X, const float* __restrict__ Wc,
                        const float* __restrict__ bias, const float* __restrict__ Res,
                        const float* __restrict__ lng, const float* __restrict__ lnb,
                        float* __restrict__ out)
{
    __shared__ float ws[64][2][64];
    __shared__ __align__(16) float xs[2][64][24]; // reused as post-relu buffer for LN
    __shared__ float mu_s[2][24], rs_s[2][24];
    int b = blockIdx.y, n0 = blockIdx.x*2;
    int tid = threadIdx.x;                        // 128
    for (int e = tid; e < 8192; e += 128) {
        int c = e >> 7, tap = (e >> 6) & 1, o = e & 63;
        ws[c][tap][o] = Wc[(o << 7) + (c << 1) + tap];
    }
    for (int e = tid; e < 3072; e += 128)
        ((float*)xs)[e] = X[((long)b*1000 + n0)*1536 + e];
    __syncthreads();
    int o = tid & 63, ni = tid >> 6;
    int n = n0 + ni;
    float bv = bias[o];
    float acc[24];
#pragma unroll
    for (int t = 0; t < 24; t++) acc[t] = bv;
#pragma unroll 2
    for (int c = 0; c < 64; c++) {
        float w0 = ws[c][0][o], w1 = ws[c][1][o];
        float xv[24];
        const float4* xr = (const float4*)xs[ni][c];
#pragma unroll
        for (int q = 0; q < 6; q++) *(float4*)&xv[q*4] = xr[q];
        acc[0] += w1*xv[0];
        acc[1] += w1*xv[1];
#pragma unroll
        for (int t = 2; t < 24; t++) acc[t] += w1*xv[t] + w0*xv[t-2];
    }
    // relu(conv2), + residual, relu
    float rv[24];
    const float4* rp = (const float4*)&Res[(((long)b*1000 + n)*64 + o)*24];
#pragma unroll
    for (int q = 0; q < 6; q++) *(float4*)&rv[q*4] = rp[q];
#pragma unroll
    for (int t = 0; t < 24; t++)
        acc[t] = fmaxf(fmaxf(acc[t], 0.f) + rv[t], 0.f);
    __syncthreads();        // done reading xs
    float* sb = &xs[ni][o][0];
#pragma unroll
    for (int q = 0; q < 6; q++) *(float4*)&sb[q*4] = *(float4*)&acc[q*4];
    __syncthreads();
    if (tid < 48) {
        int nj = tid / 24, t = tid - nj*24;
        float s = 0.f;
#pragma unroll 8
        for (int oc = 0; oc < 64; oc++) s += xs[nj][oc][t];
        float m = s * (1.f/64.f);
        float ss = 0.f;
#pragma unroll 8
        for (int oc = 0; oc < 64; oc++) { float d = xs[nj][oc][t] - m; ss += d*d; }
        mu_s[nj][t] = m;
        rs_s[nj][t] = rsqrtf(ss*(1.f/64.f) + 1e-5f);
    }
    __syncthreads();
    float g = lng[o], be = lnb[o];
    float ov[24];
#pragma unroll
    for (int t = 0; t < 24; t++)
        ov[t] = (acc[t] - mu_s[ni][t])*rs_s[ni][t]*g + be;
    float* op = &out[(((long)b*64 + o)*1000 + n)*24];
#pragma unroll
    for (int q = 0; q < 6; q++) *(float4*)&op[q*4] = *(float4*)&ov[q*4];
}

// ---------------- launch ----------------
extern "C" void kernel_launch(void* const* d_in, const int* in_sizes, int n_in,
                              void* d_out, int out_size)
{
    const float* x        = (const float*)d_in[0];
    const float* A_adj    = (const float*)d_in[1];
    const float* att0_W1  = (const float*)d_in[2];
    const float* att0_W2  = (const float*)d_in[3];
    const float* gatt_W1  = (const float*)d_in[4];
    const float* gatt_W2  = (const float*)d_in[5];
    const float* gcn_W    = (const float*)d_in[6];
    const float* tatt_W1  = (const float*)d_in[7];
    const float* tatt_W2  = (const float*)d_in[8];
    const float* conv1_w  = (const float*)d_in[9];
    const float* conv1_b  = (const float*)d_in[10];
    const float* conv2_w  = (const float*)d_in[11];
    const float* conv2_b  = (const float*)d_in[12];
    const float* res_w    = (const float*)d_in[13];
    const float* res_b    = (const float*)d_in[14];
    const float* ln_g     = (const float*)d_in[15];
    const float* ln_b     = (const float*)d_in[16];
    float* out = (float*)d_out;

    float *pproj, *patt0, *ptatt, *pAg, *px1, *pxw, *pg2, *pres, *px2b, *ppart;
    cudaGetSymbolAddress((void**)&pproj, g_proj);
    cudaGetSymbolAddress((void**)&patt0, g_att0A);
    cudaGetSymbolAddress((void**)&ptatt, g_tattA);
    cudaGetSymbolAddress((void**)&pAg,   g_Ag);
    cudaGetSymbolAddress((void**)&px1,   g_x1);
    cudaGetSymbolAddress((void**)&pxw,   g_xw);
    cudaGetSymbolAddress((void**)&pg2,   g_g2);
    cudaGetSymbolAddress((void**)&pres,  g_res);
    cudaGetSymbolAddress((void**)&px2b,  g_x2b);
    cudaGetSymbolAddress((void**)&ppart, g_part);

    // ---- att0: channel attention over C=64, dk = N*T = 24000
    k_proj  <<<dim3(64,8),   256>>>(x, att0_W1, att0_W2, pproj, 24000, 24000, 1536000L, 24000, 0);
    k_scores<<<dim3(64,8),   256>>>(pproj, nullptr, patt0, 64, 1.0f/sqrtf(24000.f));
    // x1 = att0 @ xf : M=64, N=24000, K=64 per batch
    k_sgemm <<<dim3(188,1,8),256>>>(patt0, x, px1, 64, 24000, 64, 4096L, 1536000L, 1536000L);

    // ---- gatt: graph attention over N=1000, dk = C*T = 1536
    k_proj  <<<dim3(1000,8), 256>>>(px1, gatt_W1, gatt_W2, pproj, 1536, 24, 1536000L, 24, 24000);
    k_scores<<<dim3(1000,8), 256>>>(pproj, A_adj, pAg, 1000, 1.0f/sqrtf(1536.f));

    // ---- GCN: xw = x1 x gcn_W (channel mix), then g2 = Ag @ xw
    k_chanmix<<<dim3(250,8), 256>>>(px1, gcn_W, nullptr, pxw, 0);
    k_sgemm  <<<dim3(12,8,8),256>>>(pAg, pxw, pg2, 1000, 1536, 1000, 1000000L, 1536000L, 1536000L);

    // ---- tatt: temporal attention over T=24, dk = N*Co = 64000 (reads pre-mix g2)
    k_proj_tatt  <<<dim3(250,8), 256>>>(pg2, tatt_W1, tatt_W2, ppart);
    k_reduce_tatt<<<8, 480>>>(ppart, pproj);
    k_scores     <<<dim3(24,8),  256>>>(pproj, nullptr, ptatt, 24, 1.0f/sqrtf(64000.f));

    // ---- residual 1x1 conv (independent of TCN path)
    k_chanmix<<<dim3(250,8), 256>>>(x, res_w, res_b, pres, 1);

    // ---- TCN: (tatt-mix + conv1) then (conv2 + residual + relu + LN) -> out [B,Co,N,T]
    k_conv1t<<<dim3(500,8), 128>>>(pg2, ptatt, conv1_w, conv1_b, px2b);
    k_final <<<dim3(500,8), 128>>>(px2b, conv2_w, conv2_b, pres, ln_g, ln_b, out);
}